// round 5
// baseline (speedup 1.0000x reference)
#include <cuda_runtime.h>

// RepeatDecoder: B=1024, S=200, H=128, VOCAB=100000
//   features = tanh(hidden + hidden[:,0:1,:])
//   scores   = features @ w_proj + b_proj ; mask PAD/INTEREST -> -inf
//   attn     = softmax(scores, axis=-1)
//   out[b, input_ids[b,s]] += attn[b,s]   (out zero elsewhere)
//
// R5: interleave output zeroing (write stream) with score compute (read
// stream) so DRAM stays busy the whole kernel; shfl-based softmax (4 barriers).

#define RD_VOCAB 100000
#define RD_PAD_ID (RD_VOCAB - 2)
#define RD_INTEREST_ID (RD_VOCAB - 1)
#define RD_B 1024
#define RD_S 200
#define RD_H 128
#define RD_THREADS 256
#define RD_WARPS (RD_THREADS / 32)
#define RD_ITERS (RD_S / RD_WARPS)        // 25
#define RD_ROW4 (RD_VOCAB / 4)            // 25000 float4 per row

__device__ __forceinline__ float fast_tanhf(float x) {
    float r;
    asm("tanh.approx.f32 %0, %1;" : "=f"(r) : "f"(x));
    return r;
}

__global__ __launch_bounds__(RD_THREADS, 4)
void repeat_decoder_kernel(const float* __restrict__ hidden,
                           const int* __restrict__ ids,
                           const float* __restrict__ w_proj,
                           const float* __restrict__ b_proj,
                           float* __restrict__ out)
{
    __shared__ float s_scores[RD_S];
    __shared__ float s_part[RD_WARPS];
    __shared__ float s_bcast;

    const int b    = blockIdx.x;
    const int tid  = threadIdx.x;
    const int warp = tid >> 5;
    const int lane = tid & 31;

    const float* hb = hidden + (size_t)b * RD_S * RD_H;
    float* row = out + (size_t)b * RD_VOCAB;
    float4* row4 = reinterpret_cast<float4*>(row);
    const float4 z = make_float4(0.f, 0.f, 0.f, 0.f);

    // Per-lane constants: 4 elems of w_proj and of keys (= hidden[b,0,:])
    const float4 w4 = reinterpret_cast<const float4*>(w_proj)[lane];
    const float4 k4 = reinterpret_cast<const float4*>(hb)[lane];
    const float  bias = b_proj[0];

    // --- Fused phase: zero the output row (write stream) interleaved with
    //     score compute (read stream). 25 iterations:
    //       stores: 4 strided float4 per thread (4 KB * 4 per block-iter)
    //       scores: warp `warp` handles position s = it*8 + warp
    //     1-deep prefetch on the score load to overlap latency.
    float4 h4 = reinterpret_cast<const float4*>(hb + warp * RD_H)[lane];

    #pragma unroll 1
    for (int it = 0; it < RD_ITERS; ++it) {
        // ---- write stream: 1024 float4 slots, guard against 25000 ----
        #pragma unroll
        for (int k = 0; k < 4; ++k) {
            int idx = (it * 4 + k) * RD_THREADS + tid;
            if (idx < RD_ROW4) row4[idx] = z;
        }

        // ---- prefetch next score row ----
        float4 hn;
        if (it + 1 < RD_ITERS)
            hn = reinterpret_cast<const float4*>(hb + ((it + 1) * RD_WARPS + warp) * RD_H)[lane];

        // ---- score for s = it*8 + warp ----
        float p = fast_tanhf(h4.x + k4.x) * w4.x;
        p = fmaf(fast_tanhf(h4.y + k4.y), w4.y, p);
        p = fmaf(fast_tanhf(h4.z + k4.z), w4.z, p);
        p = fmaf(fast_tanhf(h4.w + k4.w), w4.w, p);
        #pragma unroll
        for (int off = 16; off > 0; off >>= 1)
            p += __shfl_xor_sync(0xFFFFFFFFu, p, off);
        if (lane == 0) s_scores[it * RD_WARPS + warp] = p + bias;

        h4 = hn;
    }
    __syncthreads();   // scores visible; all zero-stores issued & cta-ordered

    // --- softmax over S=200 (4 barriers, shfl reductions) ---
    int my_id = 0;
    bool valid = false;
    float my_score = -INFINITY;
    if (tid < RD_S) {
        my_id = ids[(size_t)b * RD_S + tid];
        valid = (my_id != RD_PAD_ID) && (my_id != RD_INTEREST_ID);
        my_score = valid ? s_scores[tid] : -INFINITY;
    }

    // block max
    float m = my_score;
    #pragma unroll
    for (int off = 16; off > 0; off >>= 1)
        m = fmaxf(m, __shfl_xor_sync(0xFFFFFFFFu, m, off));
    if (lane == 0) s_part[warp] = m;
    __syncthreads();
    if (warp == 0) {
        float v = (lane < RD_WARPS) ? s_part[lane] : -INFINITY;
        #pragma unroll
        for (int off = 4; off > 0; off >>= 1)
            v = fmaxf(v, __shfl_xor_sync(0xFFFFFFFFu, v, off));
        if (lane == 0) s_bcast = v;
    }
    __syncthreads();
    const float mx = s_bcast;

    // block sum of exp
    const float e = valid ? __expf(my_score - mx) : 0.0f;
    float sum = e;
    #pragma unroll
    for (int off = 16; off > 0; off >>= 1)
        sum += __shfl_xor_sync(0xFFFFFFFFu, sum, off);
    if (lane == 0) s_part[warp] = sum;
    __syncthreads();
    if (warp == 0) {
        float v = (lane < RD_WARPS) ? s_part[lane] : 0.0f;
        #pragma unroll
        for (int off = 4; off > 0; off >>= 1)
            v += __shfl_xor_sync(0xFFFFFFFFu, v, off);
        if (lane == 0) s_bcast = v;
    }
    __syncthreads();
    const float wgt = e * (1.0f / s_bcast);

    // --- scatter-add (row is block-private; stores ordered by barriers) ---
    if (tid < RD_S && valid)
        atomicAdd(row + my_id, wgt);
}

extern "C" void kernel_launch(void* const* d_in, const int* in_sizes, int n_in,
                              void* d_out, int out_size)
{
    const float* hidden = (const float*)d_in[0];
    const int*   ids    = (const int*)d_in[1];
    const float* w_proj = (const float*)d_in[2];
    const float* b_proj = (const float*)d_in[3];
    float*       out    = (float*)d_out;

    repeat_decoder_kernel<<<RD_B, RD_THREADS>>>(hidden, ids, w_proj, b_proj, out);
}

// round 6
// speedup vs baseline: 1.0129x; 1.0129x over previous
#include <cuda_runtime.h>

// RepeatDecoder: B=1024, S=200, H=128, VOCAB=100000
//   features = tanh(hidden + hidden[:,0:1,:])
//   scores   = features @ w_proj + b_proj ; mask PAD/INTEREST -> -inf
//   attn     = softmax(scores, axis=-1)
//   out[b, input_ids[b,s]] += attn[b,s]   (out zero elsewhere)
//
// R6: split into a pure-read compute kernel (weights -> scratch) and a
// pure-write zero+scatter kernel with streaming (evict-first) stores.

#define RD_VOCAB 100000
#define RD_PAD_ID (RD_VOCAB - 2)
#define RD_INTEREST_ID (RD_VOCAB - 1)
#define RD_B 1024
#define RD_S 200
#define RD_H 128
#define RD_THREADS 256
#define RD_WARPS (RD_THREADS / 32)
#define RD_ROW4 (RD_VOCAB / 4)   // 25000 float4 per row

// Scratch: per-position attention weights (0 for masked positions). 800 KB.
__device__ float g_wgt[RD_B * RD_S];

__device__ __forceinline__ float fast_tanhf(float x) {
    float r;
    asm("tanh.approx.f32 %0, %1;" : "=f"(r) : "f"(x));
    return r;
}

// ---------------------------------------------------------------------------
// Kernel 1: compute softmax weights per row -> g_wgt.  Pure read stream.
// ---------------------------------------------------------------------------
__global__ __launch_bounds__(RD_THREADS, 8)
void rd_compute_kernel(const float* __restrict__ hidden,
                       const int* __restrict__ ids,
                       const float* __restrict__ w_proj,
                       const float* __restrict__ b_proj)
{
    __shared__ float s_scores[RD_S];
    __shared__ float s_part[RD_WARPS];
    __shared__ float s_bcast;

    const int b    = blockIdx.x;
    const int tid  = threadIdx.x;
    const int warp = tid >> 5;
    const int lane = tid & 31;

    const float* hb = hidden + (size_t)b * RD_S * RD_H;

    const float4 w4 = reinterpret_cast<const float4*>(w_proj)[lane];
    const float4 k4 = reinterpret_cast<const float4*>(hb)[lane];
    const float  bias = b_proj[0];

    // warp-per-position scores (8 warps, 25 iters)
    for (int s = warp; s < RD_S; s += RD_WARPS) {
        const float4 h4 = reinterpret_cast<const float4*>(hb + s * RD_H)[lane];
        float p = fast_tanhf(h4.x + k4.x) * w4.x;
        p = fmaf(fast_tanhf(h4.y + k4.y), w4.y, p);
        p = fmaf(fast_tanhf(h4.z + k4.z), w4.z, p);
        p = fmaf(fast_tanhf(h4.w + k4.w), w4.w, p);
        #pragma unroll
        for (int off = 16; off > 0; off >>= 1)
            p += __shfl_xor_sync(0xFFFFFFFFu, p, off);
        if (lane == 0) s_scores[s] = p + bias;
    }
    __syncthreads();

    // mask + softmax over S=200 (shfl reductions, 4 barriers)
    bool valid = false;
    float my_score = -INFINITY;
    if (tid < RD_S) {
        const int id = ids[(size_t)b * RD_S + tid];
        valid = (id != RD_PAD_ID) && (id != RD_INTEREST_ID);
        my_score = valid ? s_scores[tid] : -INFINITY;
    }

    float m = my_score;
    #pragma unroll
    for (int off = 16; off > 0; off >>= 1)
        m = fmaxf(m, __shfl_xor_sync(0xFFFFFFFFu, m, off));
    if (lane == 0) s_part[warp] = m;
    __syncthreads();
    if (warp == 0) {
        float v = (lane < RD_WARPS) ? s_part[lane] : -INFINITY;
        #pragma unroll
        for (int off = 4; off > 0; off >>= 1)
            v = fmaxf(v, __shfl_xor_sync(0xFFFFFFFFu, v, off));
        if (lane == 0) s_bcast = v;
    }
    __syncthreads();
    const float mx = s_bcast;

    const float e = valid ? __expf(my_score - mx) : 0.0f;
    float sum = e;
    #pragma unroll
    for (int off = 16; off > 0; off >>= 1)
        sum += __shfl_xor_sync(0xFFFFFFFFu, sum, off);
    if (lane == 0) s_part[warp] = sum;
    __syncthreads();
    if (warp == 0) {
        float v = (lane < RD_WARPS) ? s_part[lane] : 0.0f;
        #pragma unroll
        for (int off = 4; off > 0; off >>= 1)
            v += __shfl_xor_sync(0xFFFFFFFFu, v, off);
        if (lane == 0) s_bcast = v;
    }
    __syncthreads();

    if (tid < RD_S)
        g_wgt[(size_t)b * RD_S + tid] = e * (1.0f / s_bcast);
}

// ---------------------------------------------------------------------------
// Kernel 2: zero output row (streaming stores) then scatter-add. Pure write.
// ---------------------------------------------------------------------------
__global__ __launch_bounds__(RD_THREADS, 8)
void rd_zero_scatter_kernel(const int* __restrict__ ids,
                            float* __restrict__ out)
{
    const int b   = blockIdx.x;
    const int tid = threadIdx.x;

    float* row = out + (size_t)b * RD_VOCAB;
    float4* row4 = reinterpret_cast<float4*>(row);
    const float4 z = make_float4(0.f, 0.f, 0.f, 0.f);

    // 25000 float4 / 256 threads = 97.65 -> 12 x 8-unrolled + remainder
    // main: indices [0, 24576)
    #pragma unroll 1
    for (int base = 0; base < 24576; base += RD_THREADS * 8) {
        #pragma unroll
        for (int k = 0; k < 8; ++k)
            __stcs(&row4[base + k * RD_THREADS + tid], z);
    }
    // tail: [24576, 25000) = 424 float4
    {
        int idx = 24576 + tid;
        if (idx < RD_ROW4) __stcs(&row4[idx], z);
        idx += RD_THREADS;
        if (idx < RD_ROW4) __stcs(&row4[idx], z);
    }
    __syncthreads();

    if (tid < RD_S) {
        const float w = g_wgt[(size_t)b * RD_S + tid];
        const int   id = ids[(size_t)b * RD_S + tid];
        if (id != RD_PAD_ID && id != RD_INTEREST_ID)
            atomicAdd(row + id, w);
    }
}

extern "C" void kernel_launch(void* const* d_in, const int* in_sizes, int n_in,
                              void* d_out, int out_size)
{
    const float* hidden = (const float*)d_in[0];
    const int*   ids    = (const int*)d_in[1];
    const float* w_proj = (const float*)d_in[2];
    const float* b_proj = (const float*)d_in[3];
    float*       out    = (float*)d_out;

    rd_compute_kernel<<<RD_B, RD_THREADS>>>(hidden, ids, w_proj, b_proj);
    rd_zero_scatter_kernel<<<RD_B, RD_THREADS>>>(ids, out);
}

// round 8
// speedup vs baseline: 1.1031x; 1.0891x over previous
#include <cuda_runtime.h>

// RepeatDecoder: B=1024, S=200, H=128, VOCAB=100000
//   features = tanh(hidden + hidden[:,0:1,:])
//   scores   = features @ w_proj + b_proj ; mask PAD/INTEREST -> -inf
//   attn     = softmax(scores, axis=-1)
//   out[b, input_ids[b,s]] += attn[b,s]   (out zero elsewhere)
//
// R7: k1 = pure zero (store-ceiling bound, ~74us, leave alone).
//     k2 = compute + scatter fused (2-way ILP per warp, no scratch).
//     Stream order makes k2's atomics safe after k1's zeroing.

#define RD_VOCAB 100000
#define RD_PAD_ID (RD_VOCAB - 2)
#define RD_INTEREST_ID (RD_VOCAB - 1)
#define RD_B 1024
#define RD_S 200
#define RD_H 128
#define RD_THREADS 256
#define RD_WARPS (RD_THREADS / 32)
#define RD_ROW4 (RD_VOCAB / 4)   // 25000 float4 per row

__device__ __forceinline__ float fast_tanhf(float x) {
    float r;
    asm("tanh.approx.f32 %0, %1;" : "=f"(r) : "f"(x));
    return r;
}

// ---------------------------------------------------------------------------
// Kernel 1: zero the output. Pure write stream at the store ceiling.
// ---------------------------------------------------------------------------
__global__ __launch_bounds__(RD_THREADS, 8)
void rd_zero_kernel(float* __restrict__ out)
{
    const int b   = blockIdx.x;
    const int tid = threadIdx.x;

    float4* row4 = reinterpret_cast<float4*>(out + (size_t)b * RD_VOCAB);
    const float4 z = make_float4(0.f, 0.f, 0.f, 0.f);

    // main: [0, 24576) as 12 x 8-unrolled sweeps of 256 threads
    #pragma unroll 1
    for (int base = 0; base < 24576; base += RD_THREADS * 8) {
        #pragma unroll
        for (int k = 0; k < 8; ++k)
            __stcs(&row4[base + k * RD_THREADS + tid], z);
    }
    // tail: [24576, 25000)
    int idx = 24576 + tid;
    if (idx < RD_ROW4) __stcs(&row4[idx], z);
    idx += RD_THREADS;
    if (idx < RD_ROW4) __stcs(&row4[idx], z);
}

// ---------------------------------------------------------------------------
// Kernel 2: scores -> softmax -> scatter. Read stream with 2-way warp ILP.
// ---------------------------------------------------------------------------
__global__ __launch_bounds__(RD_THREADS)
void rd_compute_scatter_kernel(const float* __restrict__ hidden,
                               const int* __restrict__ ids,
                               const float* __restrict__ w_proj,
                               const float* __restrict__ b_proj,
                               float* __restrict__ out)
{
    __shared__ float s_scores[RD_S];
    __shared__ float s_part[RD_WARPS];
    __shared__ float s_bcast;

    const int b    = blockIdx.x;
    const int tid  = threadIdx.x;
    const int warp = tid >> 5;
    const int lane = tid & 31;

    const float* hb = hidden + (size_t)b * RD_S * RD_H;

    const float4 w4 = reinterpret_cast<const float4*>(w_proj)[lane];
    const float4 k4 = reinterpret_cast<const float4*>(hb)[lane];
    const float  bias = b_proj[0];

    // Two positions per warp per iteration: s0 = it*16+warp, s1 = s0+8.
    // s0 is always < 200 (max 12*16+7=199); s1 needs a guard on the last iter.
    #pragma unroll 1
    for (int it = 0; it < 13; ++it) {
        const int s0 = it * 16 + warp;
        const int s1 = s0 + 8;
        const bool has1 = (s1 < RD_S);

        const float4 h0 = reinterpret_cast<const float4*>(hb + s0 * RD_H)[lane];
        float4 h1;
        if (has1) h1 = reinterpret_cast<const float4*>(hb + s1 * RD_H)[lane];

        float p0 = fast_tanhf(h0.x + k4.x) * w4.x;
        p0 = fmaf(fast_tanhf(h0.y + k4.y), w4.y, p0);
        p0 = fmaf(fast_tanhf(h0.z + k4.z), w4.z, p0);
        p0 = fmaf(fast_tanhf(h0.w + k4.w), w4.w, p0);

        float p1 = 0.0f;
        if (has1) {
            p1 = fast_tanhf(h1.x + k4.x) * w4.x;
            p1 = fmaf(fast_tanhf(h1.y + k4.y), w4.y, p1);
            p1 = fmaf(fast_tanhf(h1.z + k4.z), w4.z, p1);
            p1 = fmaf(fast_tanhf(h1.w + k4.w), w4.w, p1);
        }

        // interleaved shuffle trees (independent chains -> ILP)
        #pragma unroll
        for (int off = 16; off > 0; off >>= 1) {
            p0 += __shfl_xor_sync(0xFFFFFFFFu, p0, off);
            p1 += __shfl_xor_sync(0xFFFFFFFFu, p1, off);
        }
        if (lane == 0) {
            s_scores[s0] = p0 + bias;
            if (has1) s_scores[s1] = p1 + bias;
        }
    }
    __syncthreads();

    // mask + softmax over S=200 (shfl reductions, 4 barriers)
    int my_id = 0;
    bool valid = false;
    float my_score = -INFINITY;
    if (tid < RD_S) {
        my_id = ids[(size_t)b * RD_S + tid];
        valid = (my_id != RD_PAD_ID) && (my_id != RD_INTEREST_ID);
        my_score = valid ? s_scores[tid] : -INFINITY;
    }

    float m = my_score;
    #pragma unroll
    for (int off = 16; off > 0; off >>= 1)
        m = fmaxf(m, __shfl_xor_sync(0xFFFFFFFFu, m, off));
    if (lane == 0) s_part[warp] = m;
    __syncthreads();
    if (warp == 0) {
        float v = (lane < RD_WARPS) ? s_part[lane] : -INFINITY;
        #pragma unroll
        for (int off = 4; off > 0; off >>= 1)
            v = fmaxf(v, __shfl_xor_sync(0xFFFFFFFFu, v, off));
        if (lane == 0) s_bcast = v;
    }
    __syncthreads();
    const float mx = s_bcast;

    const float e = valid ? __expf(my_score - mx) : 0.0f;
    float sum = e;
    #pragma unroll
    for (int off = 16; off > 0; off >>= 1)
        sum += __shfl_xor_sync(0xFFFFFFFFu, sum, off);
    if (lane == 0) s_part[warp] = sum;
    __syncthreads();
    if (warp == 0) {
        float v = (lane < RD_WARPS) ? s_part[lane] : 0.0f;
        #pragma unroll
        for (int off = 4; off > 0; off >>= 1)
            v += __shfl_xor_sync(0xFFFFFFFFu, v, off);
        if (lane == 0) s_bcast = v;
    }
    __syncthreads();

    // scatter (row already zeroed by k1; stream order guarantees visibility)
    if (tid < RD_S && valid)
        atomicAdd(out + (size_t)b * RD_VOCAB + my_id, e * (1.0f / s_bcast));
}

extern "C" void kernel_launch(void* const* d_in, const int* in_sizes, int n_in,
                              void* d_out, int out_size)
{
    const float* hidden = (const float*)d_in[0];
    const int*   ids    = (const int*)d_in[1];
    const float* w_proj = (const float*)d_in[2];
    const float* b_proj = (const float*)d_in[3];
    float*       out    = (float*)d_out;

    rd_zero_kernel<<<RD_B, RD_THREADS>>>(out);
    rd_compute_scatter_kernel<<<RD_B, RD_THREADS>>>(hidden, ids, w_proj, b_proj, out);
}

// round 9
// speedup vs baseline: 1.1683x; 1.0591x over previous
#include <cuda_runtime.h>

// RepeatDecoder: B=1024, S=200, H=128, VOCAB=100000
//   features = tanh(hidden + hidden[:,0:1,:])
//   scores   = features @ w_proj + b_proj ; mask PAD/INTEREST -> -inf
//   attn     = softmax(scores, axis=-1)
//   out[b, input_ids[b,s]] += attn[b,s]   (out zero elsewhere)
//
// R9: zero via cudaMemsetAsync (driver fill path — tests whether the ~5 TB/s
//     store ceiling seen by hand-written STG loops also binds the driver's
//     fill kernel). Compute+scatter kernel unchanged (at the DRAM wall).
//     Stream order keeps scatter after the memset.

#define RD_VOCAB 100000
#define RD_PAD_ID (RD_VOCAB - 2)
#define RD_INTEREST_ID (RD_VOCAB - 1)
#define RD_B 1024
#define RD_S 200
#define RD_H 128
#define RD_THREADS 256
#define RD_WARPS (RD_THREADS / 32)

__device__ __forceinline__ float fast_tanhf(float x) {
    float r;
    asm("tanh.approx.f32 %0, %1;" : "=f"(r) : "f"(x));
    return r;
}

// ---------------------------------------------------------------------------
// Compute + scatter: scores -> softmax -> atomics. Read stream, 2-way ILP.
// ---------------------------------------------------------------------------
__global__ __launch_bounds__(RD_THREADS)
void rd_compute_scatter_kernel(const float* __restrict__ hidden,
                               const int* __restrict__ ids,
                               const float* __restrict__ w_proj,
                               const float* __restrict__ b_proj,
                               float* __restrict__ out)
{
    __shared__ float s_scores[RD_S];
    __shared__ float s_part[RD_WARPS];
    __shared__ float s_bcast;

    const int b    = blockIdx.x;
    const int tid  = threadIdx.x;
    const int warp = tid >> 5;
    const int lane = tid & 31;

    const float* hb = hidden + (size_t)b * RD_S * RD_H;

    const float4 w4 = reinterpret_cast<const float4*>(w_proj)[lane];
    const float4 k4 = reinterpret_cast<const float4*>(hb)[lane];
    const float  bias = b_proj[0];

    // Two positions per warp per iteration: s0 = it*16+warp, s1 = s0+8.
    #pragma unroll 1
    for (int it = 0; it < 13; ++it) {
        const int s0 = it * 16 + warp;
        const int s1 = s0 + 8;
        const bool has1 = (s1 < RD_S);

        const float4 h0 = reinterpret_cast<const float4*>(hb + s0 * RD_H)[lane];
        float4 h1;
        if (has1) h1 = reinterpret_cast<const float4*>(hb + s1 * RD_H)[lane];

        float p0 = fast_tanhf(h0.x + k4.x) * w4.x;
        p0 = fmaf(fast_tanhf(h0.y + k4.y), w4.y, p0);
        p0 = fmaf(fast_tanhf(h0.z + k4.z), w4.z, p0);
        p0 = fmaf(fast_tanhf(h0.w + k4.w), w4.w, p0);

        float p1 = 0.0f;
        if (has1) {
            p1 = fast_tanhf(h1.x + k4.x) * w4.x;
            p1 = fmaf(fast_tanhf(h1.y + k4.y), w4.y, p1);
            p1 = fmaf(fast_tanhf(h1.z + k4.z), w4.z, p1);
            p1 = fmaf(fast_tanhf(h1.w + k4.w), w4.w, p1);
        }

        #pragma unroll
        for (int off = 16; off > 0; off >>= 1) {
            p0 += __shfl_xor_sync(0xFFFFFFFFu, p0, off);
            p1 += __shfl_xor_sync(0xFFFFFFFFu, p1, off);
        }
        if (lane == 0) {
            s_scores[s0] = p0 + bias;
            if (has1) s_scores[s1] = p1 + bias;
        }
    }
    __syncthreads();

    // mask + softmax over S=200 (shfl reductions, 4 barriers)
    int my_id = 0;
    bool valid = false;
    float my_score = -INFINITY;
    if (tid < RD_S) {
        my_id = ids[(size_t)b * RD_S + tid];
        valid = (my_id != RD_PAD_ID) && (my_id != RD_INTEREST_ID);
        my_score = valid ? s_scores[tid] : -INFINITY;
    }

    float m = my_score;
    #pragma unroll
    for (int off = 16; off > 0; off >>= 1)
        m = fmaxf(m, __shfl_xor_sync(0xFFFFFFFFu, m, off));
    if (lane == 0) s_part[warp] = m;
    __syncthreads();
    if (warp == 0) {
        float v = (lane < RD_WARPS) ? s_part[lane] : -INFINITY;
        #pragma unroll
        for (int off = 4; off > 0; off >>= 1)
            v = fmaxf(v, __shfl_xor_sync(0xFFFFFFFFu, v, off));
        if (lane == 0) s_bcast = v;
    }
    __syncthreads();
    const float mx = s_bcast;

    const float e = valid ? __expf(my_score - mx) : 0.0f;
    float sum = e;
    #pragma unroll
    for (int off = 16; off > 0; off >>= 1)
        sum += __shfl_xor_sync(0xFFFFFFFFu, sum, off);
    if (lane == 0) s_part[warp] = sum;
    __syncthreads();
    if (warp == 0) {
        float v = (lane < RD_WARPS) ? s_part[lane] : 0.0f;
        #pragma unroll
        for (int off = 4; off > 0; off >>= 1)
            v += __shfl_xor_sync(0xFFFFFFFFu, v, off);
        if (lane == 0) s_bcast = v;
    }
    __syncthreads();

    // scatter (row already zeroed by the memset; stream order guarantees it)
    if (tid < RD_S && valid)
        atomicAdd(out + (size_t)b * RD_VOCAB + my_id, e * (1.0f / s_bcast));
}

extern "C" void kernel_launch(void* const* d_in, const int* in_sizes, int n_in,
                              void* d_out, int out_size)
{
    const float* hidden = (const float*)d_in[0];
    const int*   ids    = (const int*)d_in[1];
    const float* w_proj = (const float*)d_in[2];
    const float* b_proj = (const float*)d_in[3];
    float*       out    = (float*)d_out;

    // Zero the full output via the driver fill path (graph memset node).
    cudaMemsetAsync(out, 0, (size_t)RD_B * RD_VOCAB * sizeof(float), 0);

    rd_compute_scatter_kernel<<<RD_B, RD_THREADS>>>(hidden, ids, w_proj, b_proj, out);
}